// round 13
// baseline (speedup 1.0000x reference)
#include <cuda_runtime.h>
#include <cuda_fp16.h>
#include <math.h>
#include <stdint.h>

// ---------------------------------------------------------------------------
// ChunkStickyRouter (sm_103 legacy tensor path) — R13: R12 baseline (272.9us)
// with convert_x eliminated: GEMM1's A-producer does LDG.128 fp32 -> cvt ->
// STS.128 in-ring (B stays cp.async; full barrier 512 = 256 STS + 256 cp
// arrives). Everything else byte-identical to R12.
// ---------------------------------------------------------------------------

#define NTOK  16384
#define DIM   2048
#define HID   1024
#define HID2  512
#define NCHUNK 128
#define CSEQ   32

#define BM 128
#define BN 128
#define BK 64                           // halfs (128B fp16 row per tile)
#define LDW 72                          // halfs per smem row (144B, LDSM conflict-free)
#define TILE_BYTES (128 * LDW * 2)      // 18432 per operand
#define STAGE_BYTES (2 * TILE_BYTES)
#define NSTAGE 3
#define DYN_SMEM (NSTAGE * STAGE_BYTES) // 110592

// output layout
#define OFF_RW    0
#define OFF_EIDX  131072
#define OFF_CLOG  131200
#define OFF_ENT   132224
#define OFF_UTIL  132225
#define OFF_FLIP  132233
#define OFF_CONC  132234

// scratch (no cudaMalloc allowed)
__device__ __half g_h1[(size_t)NTOK * HID];
__device__ __half g_w1t[(size_t)HID * DIM];
__device__ __half g_w2t[(size_t)HID2 * HID];
__device__ float g_S[NCHUNK * HID2];
__device__ float g_logits[NCHUNK * 8];
__device__ int   g_expert[NCHUNK];

__device__ __forceinline__ uint32_t smem_u32(const void* p) {
    return (uint32_t)__cvta_generic_to_shared(p);
}
__device__ __forceinline__ void cp16(uint32_t dst, const void* src) {
    asm volatile("cp.async.cg.shared.global [%0], [%1], 16;\n" :: "r"(dst), "l"(src));
}
__device__ __forceinline__ void mbar_init(uint32_t addr, uint32_t cnt) {
    asm volatile("mbarrier.init.shared.b64 [%0], %1;" :: "r"(addr), "r"(cnt) : "memory");
}
__device__ __forceinline__ void mbar_arrive(uint32_t addr) {
    asm volatile("mbarrier.arrive.shared.b64 _, [%0];" :: "r"(addr) : "memory");
}
__device__ __forceinline__ void cp_arrive(uint32_t addr) {
    asm volatile("cp.async.mbarrier.arrive.noinc.shared.b64 [%0];" :: "r"(addr) : "memory");
}
__device__ __forceinline__ void mbar_wait(uint32_t addr, uint32_t parity) {
    uint32_t done;
    do {
        asm volatile("{\n\t.reg .pred p;\n\t"
                     "mbarrier.try_wait.parity.shared::cta.b64 p, [%1], %2;\n\t"
                     "selp.b32 %0, 1, 0, p;\n\t}"
                     : "=r"(done) : "r"(addr), "r"(parity) : "memory");
    } while (!done);
}
__device__ __forceinline__ void ldsm4(unsigned& r0, unsigned& r1, unsigned& r2, unsigned& r3,
                                      uint32_t addr) {
    asm volatile("ldmatrix.sync.aligned.m8n8.x4.shared.b16 {%0,%1,%2,%3}, [%4];"
                 : "=r"(r0), "=r"(r1), "=r"(r2), "=r"(r3) : "r"(addr));
}
__device__ __forceinline__ void mma_f16(float& d0, float& d1, float& d2, float& d3,
                                        unsigned a0, unsigned a1, unsigned a2, unsigned a3,
                                        unsigned b0, unsigned b1) {
    asm volatile(
        "mma.sync.aligned.m16n8k16.row.col.f32.f16.f16.f32 "
        "{%0,%1,%2,%3},{%4,%5,%6,%7},{%8,%9},{%0,%1,%2,%3};\n"
        : "+f"(d0), "+f"(d1), "+f"(d2), "+f"(d3)
        : "r"(a0), "r"(a1), "r"(a2), "r"(a3), "r"(b0), "r"(b1));
}
__device__ __forceinline__ uint32_t pack_f16(float lo, float hi) {
    __half2 h = __floats2half2_rn(lo, hi);
    return *(uint32_t*)&h;
}

// WT[n][k] = fp16(W[k][n]); W is [R x Ccols] fp32
__global__ void transpose_cvt(const float* __restrict__ W, __half* __restrict__ WT,
                              int R, int Ccols) {
    __shared__ float t[32][33];
    const int tx = threadIdx.x, ty = threadIdx.y;       // (32, 8)
    const int rc = blockIdx.x * 32, cc = blockIdx.y * 32;
#pragma unroll
    for (int i = 0; i < 4; i++)
        t[ty + 8 * i][tx] = W[(size_t)(rc + ty + 8 * i) * Ccols + cc + tx];
    __syncthreads();
#pragma unroll
    for (int i = 0; i < 4; i++)
        WT[(size_t)(cc + ty + 8 * i) * R + rc + tx] = __float2half_rn(t[tx][ty + 8 * i]);
}

// fp16 GEMM: C = A[M,K] @ Bt[N,K]^T.
// EPI 0: C = fp16(relu(acc+bias)) full store; EPI 1: per-chunk col sums.
// PIPE 0: wait_group + __syncthreads; PIPE 1: mbarrier ring.
// CVT_A 1 (requires PIPE 1): A read as fp32 (A32), converted in producer regs,
//   stored via STS; full barrier = 512 arrives (256 STS + 256 cp.async).
template <int EPI, int PIPE, int CVT_A>
__global__ __launch_bounds__(256, 2)
void gemm_f16(const __half* __restrict__ A, const float* __restrict__ A32,
              const __half* __restrict__ Bt,
              const float* __restrict__ bias, __half* __restrict__ C,
              float* __restrict__ Sout, int M, int N_total, int K) {
    extern __shared__ __align__(16) char smem[];
    __shared__ __align__(8) uint64_t s_full[NSTAGE], s_empty[NSTAGE];
    __shared__ float s_colsum[BN];

    const int tid = threadIdx.x;
    const int warp = tid >> 5;
    const int lane = tid & 31;
    const int quad = lane >> 3;
    const int rsel = lane & 7;
    const int warpM = warp >> 2;     // 0..1 (64 rows)
    const int warpN = warp & 3;      // 0..3 (32 cols)
    const int bn = blockIdx.x, bm = blockIdx.y;

    if (PIPE == 1 && tid == 0) {
#pragma unroll
        for (int s = 0; s < NSTAGE; s++) {
            mbar_init(smem_u32(&s_full[s]), CVT_A ? 512 : 256);
            mbar_init(smem_u32(&s_empty[s]), 256);
        }
    }
    if (EPI == 1 && tid < BN) s_colsum[tid] = 0.f;
    __syncthreads();

    float acc[4][4][4];
#pragma unroll
    for (int i = 0; i < 4; i++)
#pragma unroll
        for (int j = 0; j < 4; j++)
#pragma unroll
            for (int r = 0; r < 4; r++) acc[i][j][r] = 0.f;

    const __half* Ablk = CVT_A ? nullptr : A + (size_t)bm * BM * K;
    const float* A32blk = CVT_A ? A32 + (size_t)bm * BM * K : nullptr;
    const __half* Bblk = Bt + (size_t)bn * BN * K;

    const uint32_t smem_base = smem_u32(smem);
    const int crow = tid >> 3;          // +32 per i
    const int ccb = (tid & 7) * 16;     // byte offset in smem row (16B chunk)
    const int cch = (tid & 7) * 8;      // half offset in gmem row

    auto produce = [&](int t) {
        const int s = t % NSTAGE;
        const uint32_t st = smem_base + s * STAGE_BYTES;
        const __half* Bg = Bblk + (size_t)t * BK;
        if (CVT_A) {
            const float* Ag = A32blk + (size_t)t * BK;
#pragma unroll
            for (int i = 0; i < 4; i++) {
                int r = crow + 32 * i;
                const float* src = Ag + (size_t)r * K + cch;
                float4 u = *(const float4*)src;
                float4 v = *(const float4*)(src + 4);
                uint4 o;
                o.x = pack_f16(u.x, u.y);
                o.y = pack_f16(u.z, u.w);
                o.z = pack_f16(v.x, v.y);
                o.w = pack_f16(v.z, v.w);
                *(uint4*)(smem + (size_t)(s * STAGE_BYTES) + r * (LDW * 2) + ccb) = o;
            }
        } else {
            const __half* Ag = Ablk + (size_t)t * BK;
#pragma unroll
            for (int i = 0; i < 4; i++) {
                int r = crow + 32 * i;
                cp16(st + r * (LDW * 2) + ccb, Ag + (size_t)r * K + cch);
            }
        }
#pragma unroll
        for (int i = 0; i < 4; i++) {
            int r = crow + 32 * i;
            cp16(st + TILE_BYTES + r * (LDW * 2) + ccb, Bg + (size_t)r * K + cch);
        }
        if (PIPE == 1) {
            if (CVT_A) mbar_arrive(smem_u32(&s_full[s]));  // A STS done (release)
            cp_arrive(smem_u32(&s_full[s]));               // B cp.async done
        } else {
            asm volatile("cp.async.commit_group;\n");
        }
    };

    // ldmatrix per-thread offsets (halfs)
    const int a_roff = (quad & 1) * 8 + rsel;
    const int a_coff = (quad >> 1) * 8;
    const int b_roff = (quad >> 1) * 8 + rsel;
    const int b_coff = (quad & 1) * 8;

    auto compute_tile = [&](int t) {
        const int s = t % NSTAGE;
        const uint32_t aS = smem_base + s * STAGE_BYTES;
        const uint32_t bS = aS + TILE_BYTES;
#pragma unroll
        for (int ks = 0; ks < 4; ks++) {
            const int k0 = ks * 16;
            unsigned af[4][4], bf[4][2];
#pragma unroll
            for (int mi = 0; mi < 4; mi++) {
                uint32_t addr = aS + ((warpM * 64 + mi * 16 + a_roff) * LDW + k0 + a_coff) * 2;
                ldsm4(af[mi][0], af[mi][1], af[mi][2], af[mi][3], addr);
            }
#pragma unroll
            for (int nip = 0; nip < 4; nip += 2) {
                uint32_t addr = bS + ((warpN * 32 + nip * 8 + b_roff) * LDW + k0 + b_coff) * 2;
                ldsm4(bf[nip][0], bf[nip][1], bf[nip + 1][0], bf[nip + 1][1], addr);
            }
            // done READING stage s after this warp's last LDSM (per-thread arrive)
            if (PIPE == 1 && ks == 3) mbar_arrive(smem_u32(&s_empty[s]));
#pragma unroll
            for (int mi = 0; mi < 4; mi++)
#pragma unroll
                for (int ni = 0; ni < 4; ni++)
                    mma_f16(acc[mi][ni][0], acc[mi][ni][1], acc[mi][ni][2], acc[mi][ni][3],
                            af[mi][0], af[mi][1], af[mi][2], af[mi][3],
                            bf[ni][0], bf[ni][1]);
        }
    };

    const int KT = K / BK;
    produce(0);
    produce(1);
    if (PIPE == 1) {
        for (int t = 0; t < KT; t++) {
            const int tp = t + 2;
            if (tp < KT) {
                if (tp >= NSTAGE)
                    mbar_wait(smem_u32(&s_empty[tp % NSTAGE]),
                              (uint32_t)((tp / NSTAGE - 1) & 1));
                produce(tp);
            }
            mbar_wait(smem_u32(&s_full[t % NSTAGE]), (uint32_t)((t / NSTAGE) & 1));
            compute_tile(t);
        }
    } else {
        for (int t = 0; t < KT; t++) {
            asm volatile("cp.async.wait_group 1;\n");
            __syncthreads();
            if (t + 2 < KT) produce(t + 2);
            else asm volatile("cp.async.commit_group;\n");
            compute_tile(t);
        }
    }

    const int g = lane >> 2, tg = lane & 3;
    if (EPI == 0) {
#pragma unroll
        for (int mi = 0; mi < 4; mi++) {
            int mrow = bm * BM + warpM * 64 + mi * 16 + g;
#pragma unroll
            for (int ni = 0; ni < 4; ni++) {
                int ncol = bn * BN + warpN * 32 + ni * 8 + 2 * tg;
                float bv0 = bias[ncol], bv1 = bias[ncol + 1];
                uint32_t p0 = pack_f16(fmaxf(acc[mi][ni][0] + bv0, 0.f),
                                       fmaxf(acc[mi][ni][1] + bv1, 0.f));
                uint32_t p1 = pack_f16(fmaxf(acc[mi][ni][2] + bv0, 0.f),
                                       fmaxf(acc[mi][ni][3] + bv1, 0.f));
                *(uint32_t*)(C + (size_t)mrow * N_total + ncol) = p0;
                *(uint32_t*)(C + (size_t)(mrow + 8) * N_total + ncol) = p1;
            }
        }
    } else {
#pragma unroll
        for (int ni = 0; ni < 4; ni++) {
#pragma unroll
            for (int p = 0; p < 2; p++) {
                int nloc = warpN * 32 + ni * 8 + 2 * tg + p;
                float bv = bias[bn * BN + nloc];
                float s = 0.f;
#pragma unroll
                for (int mi = 0; mi < 4; mi++) {
                    s += fmaxf(acc[mi][ni][p] + bv, 0.f);
                    s += fmaxf(acc[mi][ni][p + 2] + bv, 0.f);
                }
                s += __shfl_xor_sync(0xffffffffu, s, 4);
                s += __shfl_xor_sync(0xffffffffu, s, 8);
                s += __shfl_xor_sync(0xffffffffu, s, 16);
                if (g == 0) atomicAdd(&s_colsum[nloc], s);
            }
        }
        __syncthreads();
        if (tid < BN)
            Sout[(size_t)bm * N_total + bn * BN + tid] = s_colsum[tid];
    }
}

// chunk_logits[c][e] = (1/128) * S[c][:] . w3[:,e] + b3[e]   (128 CTAs — R9 exact)
__global__ void chunk_logits_kernel(const float* __restrict__ w3,
                                    const float* __restrict__ b3,
                                    float* __restrict__ out) {
    const int c = blockIdx.x;
    const int tid = threadIdx.x; // 256
    float partial[8];
#pragma unroll
    for (int e = 0; e < 8; e++) partial[e] = 0.f;
    for (int k = tid; k < HID2; k += 256) {
        float sv = g_S[c * HID2 + k];
        float4 wa = *(const float4*)(w3 + k * 8);
        float4 wb = *(const float4*)(w3 + k * 8 + 4);
        partial[0] += sv * wa.x; partial[1] += sv * wa.y;
        partial[2] += sv * wa.z; partial[3] += sv * wa.w;
        partial[4] += sv * wb.x; partial[5] += sv * wb.y;
        partial[6] += sv * wb.z; partial[7] += sv * wb.w;
    }
    __shared__ float red[256][8];
#pragma unroll
    for (int e = 0; e < 8; e++) red[tid][e] = partial[e];
    __syncthreads();
    for (int s2 = 128; s2 > 0; s2 >>= 1) {
        if (tid < s2) {
#pragma unroll
            for (int e = 0; e < 8; e++) red[tid][e] += red[tid + s2][e];
        }
        __syncthreads();
    }
    if (tid < 8) {
        float v = red[0][tid] * (1.f / 128.f) + b3[tid];
        g_logits[c * 8 + tid] = v;
        out[OFF_CLOG + c * 8 + tid] = v;
    }
}

// stats: entropy/argmax parallel; 32-step hysteresis serial (4 threads) — R9 exact
__global__ void stats_kernel(float* __restrict__ out) {
    const int tid = threadIdx.x;   // 128
    __shared__ float slog[NCHUNK][8];
    __shared__ float sent[NCHUNK];
    __shared__ int stop[NCHUNK];
    __shared__ int sfin[NCHUNK];
    __shared__ int sflip[4];
    __shared__ float sutil[8];

    float lg[8];
#pragma unroll
    for (int e = 0; e < 8; e++) {
        lg[e] = g_logits[tid * 8 + e];
        slog[tid][e] = lg[e];
    }
    int top = 0;
    float best = lg[0];
#pragma unroll
    for (int e = 1; e < 8; e++)
        if (lg[e] > best) { best = lg[e]; top = e; }
    stop[tid] = top;
    float ex[8], se = 0.f;
#pragma unroll
    for (int e = 0; e < 8; e++) { ex[e] = expf(lg[e] - best); se += ex[e]; }
    float inv = 1.f / se;
    float ent = 0.f;
#pragma unroll
    for (int e = 0; e < 8; e++) {
        float p = ex[e] * inv;
        ent -= p * logf(p + 1e-8f);
    }
    sent[tid] = ent;
    __syncthreads();

    if (tid < 4) {
        int prev = 0, flips = 0;
        for (int c = 0; c < CSEQ; c++) {
            int idx = tid * CSEQ + c;
            int t = stop[idx];
            int fin;
            if (c == 0) fin = t;
            else {
                bool sw = (slog[idx][t] - slog[idx][prev]) > 0.7f;
                flips += sw;
                fin = sw ? t : prev;
            }
            prev = fin;
            sfin[idx] = fin;
        }
        sflip[tid] = flips;
    }
    __syncthreads();

    g_expert[tid] = sfin[tid];
    out[OFF_EIDX + tid] = (float)sfin[tid];

    for (int s2 = 64; s2 > 0; s2 >>= 1) {
        if (tid < s2) sent[tid] += sent[tid + s2];
        __syncthreads();
    }
    if (tid < 8) {
        int c = 0;
        for (int i = 0; i < NCHUNK; i++) c += (sfin[i] == tid);
        float u = (float)c / (float)NCHUNK;
        sutil[tid] = u;
        out[OFF_UTIL + tid] = u;
    }
    __syncthreads();
    if (tid == 0) {
        out[OFF_ENT] = sent[0] / (float)NCHUNK;
        float nrm = 0.f;
#pragma unroll
        for (int e = 0; e < 8; e++) nrm += sutil[e] * sutil[e];
        out[OFF_CONC] = sqrtf(nrm);
        out[OFF_FLIP] = (float)(sflip[0] + sflip[1] + sflip[2] + sflip[3]) / (4.f * 31.f);
    }
}

__global__ void rw_kernel(float* __restrict__ out) {
    int i = blockIdx.x * blockDim.x + threadIdx.x;
    int o = i << 2;
    int ex = g_expert[o >> 10];
    int e0 = o & 7;
    float4 v;
    v.x = (e0 == ex) ? 1.f : 0.f;
    v.y = (e0 + 1 == ex) ? 1.f : 0.f;
    v.z = (e0 + 2 == ex) ? 1.f : 0.f;
    v.w = (e0 + 3 == ex) ? 1.f : 0.f;
    ((float4*)(out + OFF_RW))[i] = v;
}

extern "C" void kernel_launch(void* const* d_in, const int* in_sizes, int n_in,
                              void* d_out, int out_size) {
    const float* x  = (const float*)d_in[0];
    // d_in[1] = prev_expert_indices: presence => hysteresis; values unused.
    const float* w1 = (const float*)d_in[2];
    const float* b1 = (const float*)d_in[3];
    const float* w2 = (const float*)d_in[4];
    const float* b2 = (const float*)d_in[5];
    const float* w3 = (const float*)d_in[6];
    const float* b3 = (const float*)d_in[7];
    float* out = (float*)d_out;

    __half *h1, *w1t, *w2t;
    float *S;
    cudaGetSymbolAddress((void**)&h1, g_h1);
    cudaGetSymbolAddress((void**)&w1t, g_w1t);
    cudaGetSymbolAddress((void**)&w2t, g_w2t);
    cudaGetSymbolAddress((void**)&S, g_S);

    cudaFuncSetAttribute(gemm_f16<0, 1, 1>, cudaFuncAttributeMaxDynamicSharedMemorySize, DYN_SMEM);
    cudaFuncSetAttribute(gemm_f16<1, 0, 0>, cudaFuncAttributeMaxDynamicSharedMemorySize, DYN_SMEM);

    // pre-passes: weights -> transposed fp16 [N,K] (x conversion now fused into GEMM1)
    transpose_cvt<<<dim3(DIM / 32, HID / 32), dim3(32, 8)>>>(w1, w1t, DIM, HID);
    transpose_cvt<<<dim3(HID / 32, HID2 / 32), dim3(32, 8)>>>(w2, w2t, HID, HID2);

    // GEMM1 (ring + in-producer A conversion): h1 = fp16(relu(x @ w1 + b1))
    gemm_f16<0, 1, 1><<<dim3(HID / BN, NTOK / BM), 256, DYN_SMEM>>>(
        nullptr, x, w1t, b1, h1, nullptr, NTOK, HID, DIM);
    // GEMM2 (barrier, R12 exact): S[chunk] = col-sums of relu(h1 @ w2 + b2)
    gemm_f16<1, 0, 0><<<dim3(HID2 / BN, NTOK / BM), 256, DYN_SMEM>>>(
        h1, nullptr, w2t, b2, nullptr, S, NTOK, HID2, HID);

    chunk_logits_kernel<<<NCHUNK, 256>>>(w3, b3, out);
    stats_kernel<<<1, 128>>>(out);
    rw_kernel<<<128, 256>>>(out);
}

// round 14
// speedup vs baseline: 1.0988x; 1.0988x over previous
#include <cuda_runtime.h>
#include <cuda_fp16.h>
#include <math.h>
#include <stdint.h>

// ---------------------------------------------------------------------------
// ChunkStickyRouter (sm_103 legacy tensor path) — R14: R12 baseline (272.9us,
// best) with the three pre-pass kernels (convert_x + 2 weight transposes)
// fused into ONE grid-partitioned kernel. GEMMs byte-identical to R12.
// R13 lesson: producers must stay async (cp.async); sync LDG staging exposed
// ~50us of DRAM latency on the ring critical path.
// ---------------------------------------------------------------------------

#define NTOK  16384
#define DIM   2048
#define HID   1024
#define HID2  512
#define NCHUNK 128
#define CSEQ   32

#define BM 128
#define BN 128
#define BK 64                           // halfs (128B gmem row per tile)
#define LDW 72                          // halfs per smem row (144B, LDSM conflict-free)
#define TILE_BYTES (128 * LDW * 2)      // 18432 per operand
#define STAGE_BYTES (2 * TILE_BYTES)
#define NSTAGE 3
#define DYN_SMEM (NSTAGE * STAGE_BYTES) // 110592

// prepass grid partition
#define PP_CVT_BLOCKS   16384           // x: 16384*2048 floats / (256 thr * 8)
#define PP_W1_BLOCKS    2048            // (DIM/32)*(HID/32)
#define PP_W2_BLOCKS    512             // (HID/32)*(HID2/32)
#define PP_TOTAL (PP_CVT_BLOCKS + PP_W1_BLOCKS + PP_W2_BLOCKS)

// output layout
#define OFF_RW    0
#define OFF_EIDX  131072
#define OFF_CLOG  131200
#define OFF_ENT   132224
#define OFF_UTIL  132225
#define OFF_FLIP  132233
#define OFF_CONC  132234

// scratch (no cudaMalloc allowed)
__device__ __half g_xh[(size_t)NTOK * DIM];
__device__ __half g_h1[(size_t)NTOK * HID];
__device__ __half g_w1t[(size_t)HID * DIM];
__device__ __half g_w2t[(size_t)HID2 * HID];
__device__ float g_S[NCHUNK * HID2];
__device__ float g_logits[NCHUNK * 8];
__device__ int   g_expert[NCHUNK];

__device__ __forceinline__ uint32_t smem_u32(const void* p) {
    return (uint32_t)__cvta_generic_to_shared(p);
}
__device__ __forceinline__ void cp16(uint32_t dst, const void* src) {
    asm volatile("cp.async.cg.shared.global [%0], [%1], 16;\n" :: "r"(dst), "l"(src));
}
__device__ __forceinline__ void mbar_init(uint32_t addr, uint32_t cnt) {
    asm volatile("mbarrier.init.shared.b64 [%0], %1;" :: "r"(addr), "r"(cnt) : "memory");
}
__device__ __forceinline__ void mbar_arrive(uint32_t addr) {
    asm volatile("mbarrier.arrive.shared.b64 _, [%0];" :: "r"(addr) : "memory");
}
__device__ __forceinline__ void cp_arrive(uint32_t addr) {
    asm volatile("cp.async.mbarrier.arrive.noinc.shared.b64 [%0];" :: "r"(addr) : "memory");
}
__device__ __forceinline__ void mbar_wait(uint32_t addr, uint32_t parity) {
    uint32_t done;
    do {
        asm volatile("{\n\t.reg .pred p;\n\t"
                     "mbarrier.try_wait.parity.shared::cta.b64 p, [%1], %2;\n\t"
                     "selp.b32 %0, 1, 0, p;\n\t}"
                     : "=r"(done) : "r"(addr), "r"(parity) : "memory");
    } while (!done);
}
__device__ __forceinline__ void ldsm4(unsigned& r0, unsigned& r1, unsigned& r2, unsigned& r3,
                                      uint32_t addr) {
    asm volatile("ldmatrix.sync.aligned.m8n8.x4.shared.b16 {%0,%1,%2,%3}, [%4];"
                 : "=r"(r0), "=r"(r1), "=r"(r2), "=r"(r3) : "r"(addr));
}
__device__ __forceinline__ void mma_f16(float& d0, float& d1, float& d2, float& d3,
                                        unsigned a0, unsigned a1, unsigned a2, unsigned a3,
                                        unsigned b0, unsigned b1) {
    asm volatile(
        "mma.sync.aligned.m16n8k16.row.col.f32.f16.f16.f32 "
        "{%0,%1,%2,%3},{%4,%5,%6,%7},{%8,%9},{%0,%1,%2,%3};\n"
        : "+f"(d0), "+f"(d1), "+f"(d2), "+f"(d3)
        : "r"(a0), "r"(a1), "r"(a2), "r"(a3), "r"(b0), "r"(b1));
}
__device__ __forceinline__ uint32_t pack_f16(float lo, float hi) {
    __half2 h = __floats2half2_rn(lo, hi);
    return *(uint32_t*)&h;
}

// Fused pre-pass: blocks [0, 16384) convert x->fp16 (8 floats/thread);
// blocks [16384, 18432) transpose+cvt w1; blocks [18432, 18944) w2.
__global__ void prepass(const float* __restrict__ x,
                        const float* __restrict__ w1,
                        const float* __restrict__ w2) {
    __shared__ float t[32][33];
    const int bid = blockIdx.x;
    const int tid = threadIdx.x;

    if (bid < PP_CVT_BLOCKS) {
        size_t i = (size_t)bid * 256 + tid;
        float4 v0 = ((const float4*)x)[2 * i];
        float4 v1 = ((const float4*)x)[2 * i + 1];
        uint4 o;
        o.x = pack_f16(v0.x, v0.y);
        o.y = pack_f16(v0.z, v0.w);
        o.z = pack_f16(v1.x, v1.y);
        o.w = pack_f16(v1.z, v1.w);
        ((uint4*)g_xh)[i] = o;
        return;
    }

    // transpose job: WT[n][k] = fp16(W[k][n]) for a 32x32 block
    const float* W;
    __half* WT;
    int R, Ccols, rb;
    if (bid < PP_CVT_BLOCKS + PP_W1_BLOCKS) {
        rb = bid - PP_CVT_BLOCKS;
        W = w1; WT = g_w1t; R = DIM; Ccols = HID;
        // grid was (DIM/32=64, HID/32=32): bx = rb & 63, by = rb >> 6
        int bx = rb & 63, by = rb >> 6;
        rb = bx * 32 + (by << 16);  // pack rc in low, cc block idx in high
    } else {
        rb = bid - PP_CVT_BLOCKS - PP_W1_BLOCKS;
        W = w2; WT = g_w2t; R = HID; Ccols = HID2;
        // grid was (HID/32=32, HID2/32=16): bx = rb & 31, by = rb >> 5
        int bx = rb & 31, by = rb >> 5;
        rb = bx * 32 + (by << 16);
    }
    const int rc = rb & 0xFFFF;
    const int cc = (rb >> 16) * 32;
    const int tx = tid & 31, ty = tid >> 5;   // (32, 8)
#pragma unroll
    for (int i = 0; i < 4; i++)
        t[ty + 8 * i][tx] = W[(size_t)(rc + ty + 8 * i) * Ccols + cc + tx];
    __syncthreads();
#pragma unroll
    for (int i = 0; i < 4; i++)
        WT[(size_t)(cc + ty + 8 * i) * R + rc + tx] = __float2half_rn(t[tx][ty + 8 * i]);
}

// fp16 GEMM: C = A[M,K] @ Bt[N,K]^T.   (byte-identical to R12)
// EPI 0: C = fp16(relu(acc+bias)) full store; EPI 1: per-chunk col sums.
// PIPE 0: wait_group + __syncthreads; PIPE 1: mbarrier ring (256-cnt arrives).
template <int EPI, int PIPE>
__global__ __launch_bounds__(256, 2)
void gemm_f16(const __half* __restrict__ A, const __half* __restrict__ Bt,
              const float* __restrict__ bias, __half* __restrict__ C,
              float* __restrict__ Sout, int M, int N_total, int K) {
    extern __shared__ __align__(16) char smem[];
    __shared__ __align__(8) uint64_t s_full[NSTAGE], s_empty[NSTAGE];
    __shared__ float s_colsum[BN];

    const int tid = threadIdx.x;
    const int warp = tid >> 5;
    const int lane = tid & 31;
    const int quad = lane >> 3;
    const int rsel = lane & 7;
    const int warpM = warp >> 2;     // 0..1 (64 rows)
    const int warpN = warp & 3;      // 0..3 (32 cols)
    const int bn = blockIdx.x, bm = blockIdx.y;

    if (PIPE == 1 && tid == 0) {
#pragma unroll
        for (int s = 0; s < NSTAGE; s++) {
            mbar_init(smem_u32(&s_full[s]), 256);
            mbar_init(smem_u32(&s_empty[s]), 256);
        }
    }
    if (EPI == 1 && tid < BN) s_colsum[tid] = 0.f;
    __syncthreads();

    float acc[4][4][4];
#pragma unroll
    for (int i = 0; i < 4; i++)
#pragma unroll
        for (int j = 0; j < 4; j++)
#pragma unroll
            for (int r = 0; r < 4; r++) acc[i][j][r] = 0.f;

    const __half* Ablk = A + (size_t)bm * BM * K;
    const __half* Bblk = Bt + (size_t)bn * BN * K;

    const uint32_t smem_base = smem_u32(smem);
    const int crow = tid >> 3;          // +32 per i
    const int ccb = (tid & 7) * 16;     // byte offset in smem row
    const int cch = (tid & 7) * 8;      // half offset in gmem row

    auto produce = [&](int t) {
        const int s = t % NSTAGE;
        const uint32_t st = smem_base + s * STAGE_BYTES;
        const __half* Ag = Ablk + (size_t)t * BK;
        const __half* Bg = Bblk + (size_t)t * BK;
#pragma unroll
        for (int i = 0; i < 4; i++) {
            int r = crow + 32 * i;
            cp16(st + r * (LDW * 2) + ccb, Ag + (size_t)r * K + cch);
        }
#pragma unroll
        for (int i = 0; i < 4; i++) {
            int r = crow + 32 * i;
            cp16(st + TILE_BYTES + r * (LDW * 2) + ccb, Bg + (size_t)r * K + cch);
        }
        if (PIPE == 1) cp_arrive(smem_u32(&s_full[s]));
        else asm volatile("cp.async.commit_group;\n");
    };

    // ldmatrix per-thread offsets (halfs)
    const int a_roff = (quad & 1) * 8 + rsel;
    const int a_coff = (quad >> 1) * 8;
    const int b_roff = (quad >> 1) * 8 + rsel;
    const int b_coff = (quad & 1) * 8;

    auto compute_tile = [&](int t) {
        const int s = t % NSTAGE;
        const uint32_t aS = smem_base + s * STAGE_BYTES;
        const uint32_t bS = aS + TILE_BYTES;
#pragma unroll
        for (int ks = 0; ks < 4; ks++) {
            const int k0 = ks * 16;
            unsigned af[4][4], bf[4][2];
#pragma unroll
            for (int mi = 0; mi < 4; mi++) {
                uint32_t addr = aS + ((warpM * 64 + mi * 16 + a_roff) * LDW + k0 + a_coff) * 2;
                ldsm4(af[mi][0], af[mi][1], af[mi][2], af[mi][3], addr);
            }
#pragma unroll
            for (int nip = 0; nip < 4; nip += 2) {
                uint32_t addr = bS + ((warpN * 32 + nip * 8 + b_roff) * LDW + k0 + b_coff) * 2;
                ldsm4(bf[nip][0], bf[nip][1], bf[nip + 1][0], bf[nip + 1][1], addr);
            }
            // done READING stage s after this warp's last LDSM (per-thread arrive)
            if (PIPE == 1 && ks == 3) mbar_arrive(smem_u32(&s_empty[s]));
#pragma unroll
            for (int mi = 0; mi < 4; mi++)
#pragma unroll
                for (int ni = 0; ni < 4; ni++)
                    mma_f16(acc[mi][ni][0], acc[mi][ni][1], acc[mi][ni][2], acc[mi][ni][3],
                            af[mi][0], af[mi][1], af[mi][2], af[mi][3],
                            bf[ni][0], bf[ni][1]);
        }
    };

    const int KT = K / BK;
    produce(0);
    produce(1);
    if (PIPE == 1) {
        for (int t = 0; t < KT; t++) {
            const int tp = t + 2;
            if (tp < KT) {
                if (tp >= NSTAGE)
                    mbar_wait(smem_u32(&s_empty[tp % NSTAGE]),
                              (uint32_t)((tp / NSTAGE - 1) & 1));
                produce(tp);
            }
            mbar_wait(smem_u32(&s_full[t % NSTAGE]), (uint32_t)((t / NSTAGE) & 1));
            compute_tile(t);
        }
    } else {
        for (int t = 0; t < KT; t++) {
            asm volatile("cp.async.wait_group 1;\n");
            __syncthreads();
            if (t + 2 < KT) produce(t + 2);
            else asm volatile("cp.async.commit_group;\n");
            compute_tile(t);
        }
    }

    const int g = lane >> 2, tg = lane & 3;
    if (EPI == 0) {
#pragma unroll
        for (int mi = 0; mi < 4; mi++) {
            int mrow = bm * BM + warpM * 64 + mi * 16 + g;
#pragma unroll
            for (int ni = 0; ni < 4; ni++) {
                int ncol = bn * BN + warpN * 32 + ni * 8 + 2 * tg;
                float bv0 = bias[ncol], bv1 = bias[ncol + 1];
                uint32_t p0 = pack_f16(fmaxf(acc[mi][ni][0] + bv0, 0.f),
                                       fmaxf(acc[mi][ni][1] + bv1, 0.f));
                uint32_t p1 = pack_f16(fmaxf(acc[mi][ni][2] + bv0, 0.f),
                                       fmaxf(acc[mi][ni][3] + bv1, 0.f));
                *(uint32_t*)(C + (size_t)mrow * N_total + ncol) = p0;
                *(uint32_t*)(C + (size_t)(mrow + 8) * N_total + ncol) = p1;
            }
        }
    } else {
#pragma unroll
        for (int ni = 0; ni < 4; ni++) {
#pragma unroll
            for (int p = 0; p < 2; p++) {
                int nloc = warpN * 32 + ni * 8 + 2 * tg + p;
                float bv = bias[bn * BN + nloc];
                float s = 0.f;
#pragma unroll
                for (int mi = 0; mi < 4; mi++) {
                    s += fmaxf(acc[mi][ni][p] + bv, 0.f);
                    s += fmaxf(acc[mi][ni][p + 2] + bv, 0.f);
                }
                s += __shfl_xor_sync(0xffffffffu, s, 4);
                s += __shfl_xor_sync(0xffffffffu, s, 8);
                s += __shfl_xor_sync(0xffffffffu, s, 16);
                if (g == 0) atomicAdd(&s_colsum[nloc], s);
            }
        }
        __syncthreads();
        if (tid < BN)
            Sout[(size_t)bm * N_total + bn * BN + tid] = s_colsum[tid];
    }
}

// chunk_logits[c][e] = (1/128) * S[c][:] . w3[:,e] + b3[e]   (128 CTAs)
__global__ void chunk_logits_kernel(const float* __restrict__ w3,
                                    const float* __restrict__ b3,
                                    float* __restrict__ out) {
    const int c = blockIdx.x;
    const int tid = threadIdx.x; // 256
    float partial[8];
#pragma unroll
    for (int e = 0; e < 8; e++) partial[e] = 0.f;
    for (int k = tid; k < HID2; k += 256) {
        float sv = g_S[c * HID2 + k];
        float4 wa = *(const float4*)(w3 + k * 8);
        float4 wb = *(const float4*)(w3 + k * 8 + 4);
        partial[0] += sv * wa.x; partial[1] += sv * wa.y;
        partial[2] += sv * wa.z; partial[3] += sv * wa.w;
        partial[4] += sv * wb.x; partial[5] += sv * wb.y;
        partial[6] += sv * wb.z; partial[7] += sv * wb.w;
    }
    __shared__ float red[256][8];
#pragma unroll
    for (int e = 0; e < 8; e++) red[tid][e] = partial[e];
    __syncthreads();
    for (int s2 = 128; s2 > 0; s2 >>= 1) {
        if (tid < s2) {
#pragma unroll
            for (int e = 0; e < 8; e++) red[tid][e] += red[tid + s2][e];
        }
        __syncthreads();
    }
    if (tid < 8) {
        float v = red[0][tid] * (1.f / 128.f) + b3[tid];
        g_logits[c * 8 + tid] = v;
        out[OFF_CLOG + c * 8 + tid] = v;
    }
}

// stats: entropy/argmax parallel; 32-step hysteresis serial (4 threads)
__global__ void stats_kernel(float* __restrict__ out) {
    const int tid = threadIdx.x;   // 128
    __shared__ float slog[NCHUNK][8];
    __shared__ float sent[NCHUNK];
    __shared__ int stop[NCHUNK];
    __shared__ int sfin[NCHUNK];
    __shared__ int sflip[4];
    __shared__ float sutil[8];

    float lg[8];
#pragma unroll
    for (int e = 0; e < 8; e++) {
        lg[e] = g_logits[tid * 8 + e];
        slog[tid][e] = lg[e];
    }
    int top = 0;
    float best = lg[0];
#pragma unroll
    for (int e = 1; e < 8; e++)
        if (lg[e] > best) { best = lg[e]; top = e; }
    stop[tid] = top;
    float ex[8], se = 0.f;
#pragma unroll
    for (int e = 0; e < 8; e++) { ex[e] = expf(lg[e] - best); se += ex[e]; }
    float inv = 1.f / se;
    float ent = 0.f;
#pragma unroll
    for (int e = 0; e < 8; e++) {
        float p = ex[e] * inv;
        ent -= p * logf(p + 1e-8f);
    }
    sent[tid] = ent;
    __syncthreads();

    if (tid < 4) {
        int prev = 0, flips = 0;
        for (int c = 0; c < CSEQ; c++) {
            int idx = tid * CSEQ + c;
            int t = stop[idx];
            int fin;
            if (c == 0) fin = t;
            else {
                bool sw = (slog[idx][t] - slog[idx][prev]) > 0.7f;
                flips += sw;
                fin = sw ? t : prev;
            }
            prev = fin;
            sfin[idx] = fin;
        }
        sflip[tid] = flips;
    }
    __syncthreads();

    g_expert[tid] = sfin[tid];
    out[OFF_EIDX + tid] = (float)sfin[tid];

    for (int s2 = 64; s2 > 0; s2 >>= 1) {
        if (tid < s2) sent[tid] += sent[tid + s2];
        __syncthreads();
    }
    if (tid < 8) {
        int c = 0;
        for (int i = 0; i < NCHUNK; i++) c += (sfin[i] == tid);
        float u = (float)c / (float)NCHUNK;
        sutil[tid] = u;
        out[OFF_UTIL + tid] = u;
    }
    __syncthreads();
    if (tid == 0) {
        out[OFF_ENT] = sent[0] / (float)NCHUNK;
        float nrm = 0.f;
#pragma unroll
        for (int e = 0; e < 8; e++) nrm += sutil[e] * sutil[e];
        out[OFF_CONC] = sqrtf(nrm);
        out[OFF_FLIP] = (float)(sflip[0] + sflip[1] + sflip[2] + sflip[3]) / (4.f * 31.f);
    }
}

__global__ void rw_kernel(float* __restrict__ out) {
    int i = blockIdx.x * blockDim.x + threadIdx.x;
    int o = i << 2;
    int ex = g_expert[o >> 10];
    int e0 = o & 7;
    float4 v;
    v.x = (e0 == ex) ? 1.f : 0.f;
    v.y = (e0 + 1 == ex) ? 1.f : 0.f;
    v.z = (e0 + 2 == ex) ? 1.f : 0.f;
    v.w = (e0 + 3 == ex) ? 1.f : 0.f;
    ((float4*)(out + OFF_RW))[i] = v;
}

extern "C" void kernel_launch(void* const* d_in, const int* in_sizes, int n_in,
                              void* d_out, int out_size) {
    const float* x  = (const float*)d_in[0];
    // d_in[1] = prev_expert_indices: presence => hysteresis; values unused.
    const float* w1 = (const float*)d_in[2];
    const float* b1 = (const float*)d_in[3];
    const float* w2 = (const float*)d_in[4];
    const float* b2 = (const float*)d_in[5];
    const float* w3 = (const float*)d_in[6];
    const float* b3 = (const float*)d_in[7];
    float* out = (float*)d_out;

    __half *xh, *h1, *w1t, *w2t;
    float *S;
    cudaGetSymbolAddress((void**)&xh, g_xh);
    cudaGetSymbolAddress((void**)&h1, g_h1);
    cudaGetSymbolAddress((void**)&w1t, g_w1t);
    cudaGetSymbolAddress((void**)&w2t, g_w2t);
    cudaGetSymbolAddress((void**)&S, g_S);

    cudaFuncSetAttribute(gemm_f16<0, 1>, cudaFuncAttributeMaxDynamicSharedMemorySize, DYN_SMEM);
    cudaFuncSetAttribute(gemm_f16<1, 0>, cudaFuncAttributeMaxDynamicSharedMemorySize, DYN_SMEM);

    // fused pre-pass: x -> fp16 + both weight transposes in one launch
    prepass<<<PP_TOTAL, 256>>>(x, w1, w2);

    // GEMM1 (ring, R12 exact): h1 = fp16(relu(xh @ w1 + b1))
    gemm_f16<0, 1><<<dim3(HID / BN, NTOK / BM), 256, DYN_SMEM>>>(
        xh, w1t, b1, h1, nullptr, NTOK, HID, DIM);
    // GEMM2 (barrier, R12 exact): S[chunk] = col-sums of relu(h1 @ w2 + b2)
    gemm_f16<1, 0><<<dim3(HID2 / BN, NTOK / BM), 256, DYN_SMEM>>>(
        h1, w2t, b2, nullptr, S, NTOK, HID2, HID);

    chunk_logits_kernel<<<NCHUNK, 256>>>(w3, b3, out);
    stats_kernel<<<1, 128>>>(out);
    rw_kernel<<<128, 256>>>(out);
}

// round 17
// speedup vs baseline: 1.1734x; 1.0678x over previous
#include <cuda_runtime.h>
#include <cuda_fp16.h>
#include <math.h>
#include <stdint.h>

// ---------------------------------------------------------------------------
// ChunkStickyRouter (sm_103 legacy tensor path) — R15: both GEMMs fused into
// ONE 1536-CTA kernel with per-row-block ready flags, eliminating the wave-
// quantization loss (G1: 1024 CTAs / 296 slots = 3.46 -> paid 4 waves; G2:
// 1.73 -> 2). GEMM2 CTAs (bid>=1024, dispatched after all GEMM1 by bid order
// => deadlock-free) spin on g_ready[row] and pack GEMM1's idle wave-4 slots.
// fp16 m16n8k16, mbarrier ring for both roles (R10 proved both shapes).
// ---------------------------------------------------------------------------

#define NTOK  16384
#define DIM   2048
#define HID   1024
#define HID2  512
#define NCHUNK 128
#define CSEQ   32

#define BM 128
#define BN 128
#define BK 64                           // halfs (128B gmem row per tile)
#define LDW 72                          // halfs per smem row (144B, LDSM conflict-free)
#define TILE_BYTES (128 * LDW * 2)      // 18432 per operand
#define STAGE_BYTES (2 * TILE_BYTES)
#define NSTAGE 3
#define DYN_SMEM (NSTAGE * STAGE_BYTES) // 110592

#define G1_CTAS 1024                    // (NTOK/BM)*(HID/BN) = 128*8
#define G2_CTAS 512                     // (NTOK/BM)*(HID2/BN) = 128*4

// prepass grid partition
#define PP_CVT_BLOCKS   16384
#define PP_W1_BLOCKS    2048
#define PP_W2_BLOCKS    512
#define PP_TOTAL (PP_CVT_BLOCKS + PP_W1_BLOCKS + PP_W2_BLOCKS)

// output layout
#define OFF_RW    0
#define OFF_EIDX  131072
#define OFF_CLOG  131200
#define OFF_ENT   132224
#define OFF_UTIL  132225
#define OFF_FLIP  132233
#define OFF_CONC  132234

// scratch (no cudaMalloc allowed)
__device__ __half g_xh[(size_t)NTOK * DIM];
__device__ __half g_h1[(size_t)NTOK * HID];
__device__ __half g_w1t[(size_t)HID * DIM];
__device__ __half g_w2t[(size_t)HID2 * HID];
__device__ float g_S[NCHUNK * HID2];
__device__ float g_logits[NCHUNK * 8];
__device__ int   g_expert[NCHUNK];
__device__ int   g_ready[NCHUNK];       // per-row-block completion counters

__device__ __forceinline__ uint32_t smem_u32(const void* p) {
    return (uint32_t)__cvta_generic_to_shared(p);
}
__device__ __forceinline__ void cp16(uint32_t dst, const void* src) {
    asm volatile("cp.async.cg.shared.global [%0], [%1], 16;\n" :: "r"(dst), "l"(src));
}
__device__ __forceinline__ void mbar_init(uint32_t addr, uint32_t cnt) {
    asm volatile("mbarrier.init.shared.b64 [%0], %1;" :: "r"(addr), "r"(cnt) : "memory");
}
__device__ __forceinline__ void mbar_arrive(uint32_t addr) {
    asm volatile("mbarrier.arrive.shared.b64 _, [%0];" :: "r"(addr) : "memory");
}
__device__ __forceinline__ void cp_arrive(uint32_t addr) {
    asm volatile("cp.async.mbarrier.arrive.noinc.shared.b64 [%0];" :: "r"(addr) : "memory");
}
__device__ __forceinline__ void mbar_wait(uint32_t addr, uint32_t parity) {
    uint32_t done;
    do {
        asm volatile("{\n\t.reg .pred p;\n\t"
                     "mbarrier.try_wait.parity.shared::cta.b64 p, [%1], %2;\n\t"
                     "selp.b32 %0, 1, 0, p;\n\t}"
                     : "=r"(done) : "r"(addr), "r"(parity) : "memory");
    } while (!done);
}
__device__ __forceinline__ void ldsm4(unsigned& r0, unsigned& r1, unsigned& r2, unsigned& r3,
                                      uint32_t addr) {
    asm volatile("ldmatrix.sync.aligned.m8n8.x4.shared.b16 {%0,%1,%2,%3}, [%4];"
                 : "=r"(r0), "=r"(r1), "=r"(r2), "=r"(r3) : "r"(addr));
}
__device__ __forceinline__ void mma_f16(float& d0, float& d1, float& d2, float& d3,
                                        unsigned a0, unsigned a1, unsigned a2, unsigned a3,
                                        unsigned b0, unsigned b1) {
    asm volatile(
        "mma.sync.aligned.m16n8k16.row.col.f32.f16.f16.f32 "
        "{%0,%1,%2,%3},{%4,%5,%6,%7},{%8,%9},{%0,%1,%2,%3};\n"
        : "+f"(d0), "+f"(d1), "+f"(d2), "+f"(d3)
        : "r"(a0), "r"(a1), "r"(a2), "r"(a3), "r"(b0), "r"(b1));
}
__device__ __forceinline__ uint32_t pack_f16(float lo, float hi) {
    __half2 h = __floats2half2_rn(lo, hi);
    return *(uint32_t*)&h;
}

// Fused pre-pass (R14): x->fp16, w1/w2 transpose+cvt, and zero g_ready.
__global__ void prepass(const float* __restrict__ x,
                        const float* __restrict__ w1,
                        const float* __restrict__ w2) {
    __shared__ float t[32][33];
    const int bid = blockIdx.x;
    const int tid = threadIdx.x;

    if (bid == 0 && tid < NCHUNK) g_ready[tid] = 0;

    if (bid < PP_CVT_BLOCKS) {
        size_t i = (size_t)bid * 256 + tid;
        float4 v0 = ((const float4*)x)[2 * i];
        float4 v1 = ((const float4*)x)[2 * i + 1];
        uint4 o;
        o.x = pack_f16(v0.x, v0.y);
        o.y = pack_f16(v0.z, v0.w);
        o.z = pack_f16(v1.x, v1.y);
        o.w = pack_f16(v1.z, v1.w);
        ((uint4*)g_xh)[i] = o;
        return;
    }

    const float* W;
    __half* WT;
    int R, Ccols, rb;
    if (bid < PP_CVT_BLOCKS + PP_W1_BLOCKS) {
        rb = bid - PP_CVT_BLOCKS;
        W = w1; WT = g_w1t; R = DIM; Ccols = HID;
        int bx = rb & 63, by = rb >> 6;
        rb = bx * 32 + (by << 16);
    } else {
        rb = bid - PP_CVT_BLOCKS - PP_W1_BLOCKS;
        W = w2; WT = g_w2t; R = HID; Ccols = HID2;
        int bx = rb & 31, by = rb >> 5;
        rb = bx * 32 + (by << 16);
    }
    const int rc = rb & 0xFFFF;
    const int cc = (rb >> 16) * 32;
    const int tx = tid & 31, ty = tid >> 5;
#pragma unroll
    for (int i = 0; i < 4; i++)
        t[ty + 8 * i][tx] = W[(size_t)(rc + ty + 8 * i) * Ccols + cc + tx];
    __syncthreads();
#pragma unroll
    for (int i = 0; i < 4; i++)
        WT[(size_t)(cc + ty + 8 * i) * R + rc + tx] = __float2half_rn(t[tx][ty + 8 * i]);
}

// Fused MLP: bids [0,1024) = GEMM1 (h1 = fp16(relu(xh@w1+b1)), signal row);
//            bids [1024,1536) = GEMM2 (spin on row flags, chunk col-sums).
// Ring pipeline for both roles; row-major bid order for GEMM1 so row blocks
// complete early and in order.
__global__ __launch_bounds__(256, 2)
void mlp_fused(const __half* __restrict__ xh, const __half* __restrict__ w1t,
               const __half* __restrict__ w2t,
               const float* __restrict__ b1, const float* __restrict__ b2,
               __half* __restrict__ h1, float* __restrict__ S) {
    extern __shared__ __align__(16) char smem[];
    __shared__ __align__(8) uint64_t s_full[NSTAGE], s_empty[NSTAGE];
    __shared__ float s_colsum[BN];

    const int bid = blockIdx.x;
    const int tid = threadIdx.x;
    const int warp = tid >> 5;
    const int lane = tid & 31;
    const int quad = lane >> 3;
    const int rsel = lane & 7;
    const int warpM = warp >> 2;
    const int warpN = warp & 3;

    const bool role2 = (bid >= G1_CTAS);
    int bm, bn, K;
    const __half *A, *Bt;
    const float* bias;
    if (!role2) {
        bm = bid >> 3; bn = bid & 7;           // row-major: rows finish early
        A = xh; Bt = w1t; bias = b1; K = DIM;
    } else {
        const int k2 = bid - G1_CTAS;
        bm = k2 >> 2; bn = k2 & 3;
        A = h1; Bt = w2t; bias = b2; K = HID;
    }
    const int N_total = role2 ? HID2 : HID;

    if (tid == 0) {
#pragma unroll
        for (int s = 0; s < NSTAGE; s++) {
            mbar_init(smem_u32(&s_full[s]), 256);
            mbar_init(smem_u32(&s_empty[s]), 256);
        }
    }
    if (role2 && tid < BN) s_colsum[tid] = 0.f;
    __syncthreads();

    // GEMM2: wait for this row block of h1 (8 GEMM1 CTAs). Deadlock-free:
    // bid>=1024 is dispatched only after all GEMM1 CTAs are dispatched.
    if (role2) {
        if (tid == 0) {
            while (atomicAdd(&g_ready[bm], 0) < 8) __nanosleep(64);
            __threadfence();
        }
        __syncthreads();
    }

    float acc[4][4][4];
#pragma unroll
    for (int i = 0; i < 4; i++)
#pragma unroll
        for (int j = 0; j < 4; j++)
#pragma unroll
            for (int r = 0; r < 4; r++) acc[i][j][r] = 0.f;

    const __half* Ablk = A + (size_t)bm * BM * K;
    const __half* Bblk = Bt + (size_t)bn * BN * K;

    const uint32_t smem_base = smem_u32(smem);
    const int crow = tid >> 3;
    const int ccb = (tid & 7) * 16;
    const int cch = (tid & 7) * 8;

    auto produce = [&](int t) {
        const int s = t % NSTAGE;
        const uint32_t st = smem_base + s * STAGE_BYTES;
        const __half* Ag = Ablk + (size_t)t * BK;
        const __half* Bg = Bblk + (size_t)t * BK;
#pragma unroll
        for (int i = 0; i < 4; i++) {
            int r = crow + 32 * i;
            cp16(st + r * (LDW * 2) + ccb, Ag + (size_t)r * K + cch);
        }
#pragma unroll
        for (int i = 0; i < 4; i++) {
            int r = crow + 32 * i;
            cp16(st + TILE_BYTES + r * (LDW * 2) + ccb, Bg + (size_t)r * K + cch);
        }
        cp_arrive(smem_u32(&s_full[s]));
    };

    const int a_roff = (quad & 1) * 8 + rsel;
    const int a_coff = (quad >> 1) * 8;
    const int b_roff = (quad >> 1) * 8 + rsel;
    const int b_coff = (quad & 1) * 8;

    auto compute_tile = [&](int t) {
        const int s = t % NSTAGE;
        const uint32_t aS = smem_base + s * STAGE_BYTES;
        const uint32_t bS = aS + TILE_BYTES;
#pragma unroll
        for (int ks = 0; ks < 4; ks++) {
            const int k0 = ks * 16;
            unsigned af[4][4], bf[4][2];
#pragma unroll
            for (int mi = 0; mi < 4; mi++) {
                uint32_t addr = aS + ((warpM * 64 + mi * 16 + a_roff) * LDW + k0 + a_coff) * 2;
                ldsm4(af[mi][0], af[mi][1], af[mi][2], af[mi][3], addr);
            }
#pragma unroll
            for (int nip = 0; nip < 4; nip += 2) {
                uint32_t addr = bS + ((warpN * 32 + nip * 8 + b_roff) * LDW + k0 + b_coff) * 2;
                ldsm4(bf[nip][0], bf[nip][1], bf[nip + 1][0], bf[nip + 1][1], addr);
            }
            if (ks == 3) mbar_arrive(smem_u32(&s_empty[s]));
#pragma unroll
            for (int mi = 0; mi < 4; mi++)
#pragma unroll
                for (int ni = 0; ni < 4; ni++)
                    mma_f16(acc[mi][ni][0], acc[mi][ni][1], acc[mi][ni][2], acc[mi][ni][3],
                            af[mi][0], af[mi][1], af[mi][2], af[mi][3],
                            bf[ni][0], bf[ni][1]);
        }
    };

    const int KT = K / BK;
    produce(0);
    produce(1);
    for (int t = 0; t < KT; t++) {
        const int tp = t + 2;
        if (tp < KT) {
            if (tp >= NSTAGE)
                mbar_wait(smem_u32(&s_empty[tp % NSTAGE]),
                          (uint32_t)((tp / NSTAGE - 1) & 1));
            produce(tp);
        }
        mbar_wait(smem_u32(&s_full[t % NSTAGE]), (uint32_t)((t / NSTAGE) & 1));
        compute_tile(t);
    }

    const int g = lane >> 2, tg = lane & 3;
    if (!role2) {
#pragma unroll
        for (int mi = 0; mi < 4; mi++) {
            int mrow = bm * BM + warpM * 64 + mi * 16 + g;
#pragma unroll
            for (int ni = 0; ni < 4; ni++) {
                int ncol = bn * BN + warpN * 32 + ni * 8 + 2 * tg;
                float bv0 = bias[ncol], bv1 = bias[ncol + 1];
                uint32_t p0 = pack_f16(fmaxf(acc[mi][ni][0] + bv0, 0.f),
                                       fmaxf(acc[mi][ni][1] + bv1, 0.f));
                uint32_t p1 = pack_f16(fmaxf(acc[mi][ni][2] + bv0, 0.f),
                                       fmaxf(acc[mi][ni][3] + bv1, 0.f));
                *(uint32_t*)(h1 + (size_t)mrow * N_total + ncol) = p0;
                *(uint32_t*)(h1 + (size_t)(mrow + 8) * N_total + ncol) = p1;
            }
        }
        // signal: this (bm, bn) contribution to row block bm is complete
        __threadfence();
        __syncthreads();
        if (tid == 0) atomicAdd(&g_ready[bm], 1);
    } else {
#pragma unroll
        for (int ni = 0; ni < 4; ni++) {
#pragma unroll
            for (int p = 0; p < 2; p++) {
                int nloc = warpN * 32 + ni * 8 + 2 * tg + p;
                float bv = bias[bn * BN + nloc];
                float s = 0.f;
#pragma unroll
                for (int mi = 0; mi < 4; mi++) {
                    s += fmaxf(acc[mi][ni][p] + bv, 0.f);
                    s += fmaxf(acc[mi][ni][p + 2] + bv, 0.f);
                }
                s += __shfl_xor_sync(0xffffffffu, s, 4);
                s += __shfl_xor_sync(0xffffffffu, s, 8);
                s += __shfl_xor_sync(0xffffffffu, s, 16);
                if (g == 0) atomicAdd(&s_colsum[nloc], s);
            }
        }
        __syncthreads();
        if (tid < BN)
            S[(size_t)bm * N_total + bn * BN + tid] = s_colsum[tid];
    }
}

// chunk_logits[c][e] = (1/128) * S[c][:] . w3[:,e] + b3[e]   (128 CTAs)
__global__ void chunk_logits_kernel(const float* __restrict__ w3,
                                    const float* __restrict__ b3,
                                    float* __restrict__ out) {
    const int c = blockIdx.x;
    const int tid = threadIdx.x; // 256
    float partial[8];
#pragma unroll
    for (int e = 0; e < 8; e++) partial[e] = 0.f;
    for (int k = tid; k < HID2; k += 256) {
        float sv = g_S[c * HID2 + k];
        float4 wa = *(const float4*)(w3 + k * 8);
        float4 wb = *(const float4*)(w3 + k * 8 + 4);
        partial[0] += sv * wa.x; partial[1] += sv * wa.y;
        partial[2] += sv * wa.z; partial[3] += sv * wa.w;
        partial[4] += sv * wb.x; partial[5] += sv * wb.y;
        partial[6] += sv * wb.z; partial[7] += sv * wb.w;
    }
    __shared__ float red[256][8];
#pragma unroll
    for (int e = 0; e < 8; e++) red[tid][e] = partial[e];
    __syncthreads();
    for (int s2 = 128; s2 > 0; s2 >>= 1) {
        if (tid < s2) {
#pragma unroll
            for (int e = 0; e < 8; e++) red[tid][e] += red[tid + s2][e];
        }
        __syncthreads();
    }
    if (tid < 8) {
        float v = red[0][tid] * (1.f / 128.f) + b3[tid];
        g_logits[c * 8 + tid] = v;
        out[OFF_CLOG + c * 8 + tid] = v;
    }
}

// stats: entropy/argmax parallel; 32-step hysteresis serial (4 threads)
__global__ void stats_kernel(float* __restrict__ out) {
    const int tid = threadIdx.x;   // 128
    __shared__ float slog[NCHUNK][8];
    __shared__ float sent[NCHUNK];
    __shared__ int stop[NCHUNK];
    __shared__ int sfin[NCHUNK];
    __shared__ int sflip[4];
    __shared__ float sutil[8];

    float lg[8];
#pragma unroll
    for (int e = 0; e < 8; e++) {
        lg[e] = g_logits[tid * 8 + e];
        slog[tid][e] = lg[e];
    }
    int top = 0;
    float best = lg[0];
#pragma unroll
    for (int e = 1; e < 8; e++)
        if (lg[e] > best) { best = lg[e]; top = e; }
    stop[tid] = top;
    float ex[8], se = 0.f;
#pragma unroll
    for (int e = 0; e < 8; e++) { ex[e] = expf(lg[e] - best); se += ex[e]; }
    float inv = 1.f / se;
    float ent = 0.f;
#pragma unroll
    for (int e = 0; e < 8; e++) {
        float p = ex[e] * inv;
        ent -= p * logf(p + 1e-8f);
    }
    sent[tid] = ent;
    __syncthreads();

    if (tid < 4) {
        int prev = 0, flips = 0;
        for (int c = 0; c < CSEQ; c++) {
            int idx = tid * CSEQ + c;
            int t = stop[idx];
            int fin;
            if (c == 0) fin = t;
            else {
                bool sw = (slog[idx][t] - slog[idx][prev]) > 0.7f;
                flips += sw;
                fin = sw ? t : prev;
            }
            prev = fin;
            sfin[idx] = fin;
        }
        sflip[tid] = flips;
    }
    __syncthreads();

    g_expert[tid] = sfin[tid];
    out[OFF_EIDX + tid] = (float)sfin[tid];

    for (int s2 = 64; s2 > 0; s2 >>= 1) {
        if (tid < s2) sent[tid] += sent[tid + s2];
        __syncthreads();
    }
    if (tid < 8) {
        int c = 0;
        for (int i = 0; i < NCHUNK; i++) c += (sfin[i] == tid);
        float u = (float)c / (float)NCHUNK;
        sutil[tid] = u;
        out[OFF_UTIL + tid] = u;
    }
    __syncthreads();
    if (tid == 0) {
        out[OFF_ENT] = sent[0] / (float)NCHUNK;
        float nrm = 0.f;
#pragma unroll
        for (int e = 0; e < 8; e++) nrm += sutil[e] * sutil[e];
        out[OFF_CONC] = sqrtf(nrm);
        out[OFF_FLIP] = (float)(sflip[0] + sflip[1] + sflip[2] + sflip[3]) / (4.f * 31.f);
    }
}

__global__ void rw_kernel(float* __restrict__ out) {
    int i = blockIdx.x * blockDim.x + threadIdx.x;
    int o = i << 2;
    int ex = g_expert[o >> 10];
    int e0 = o & 7;
    float4 v;
    v.x = (e0 == ex) ? 1.f : 0.f;
    v.y = (e0 + 1 == ex) ? 1.f : 0.f;
    v.z = (e0 + 2 == ex) ? 1.f : 0.f;
    v.w = (e0 + 3 == ex) ? 1.f : 0.f;
    ((float4*)(out + OFF_RW))[i] = v;
}

extern "C" void kernel_launch(void* const* d_in, const int* in_sizes, int n_in,
                              void* d_out, int out_size) {
    const float* x  = (const float*)d_in[0];
    // d_in[1] = prev_expert_indices: presence => hysteresis; values unused.
    const float* w1 = (const float*)d_in[2];
    const float* b1 = (const float*)d_in[3];
    const float* w2 = (const float*)d_in[4];
    const float* b2 = (const float*)d_in[5];
    const float* w3 = (const float*)d_in[6];
    const float* b3 = (const float*)d_in[7];
    float* out = (float*)d_out;

    __half *xh, *h1, *w1t, *w2t;
    float *S;
    cudaGetSymbolAddress((void**)&xh, g_xh);
    cudaGetSymbolAddress((void**)&h1, g_h1);
    cudaGetSymbolAddress((void**)&w1t, g_w1t);
    cudaGetSymbolAddress((void**)&w2t, g_w2t);
    cudaGetSymbolAddress((void**)&S, g_S);

    cudaFuncSetAttribute(mlp_fused, cudaFuncAttributeMaxDynamicSharedMemorySize, DYN_SMEM);

    // fused pre-pass: x -> fp16, weight transposes, zero row flags
    prepass<<<PP_TOTAL, 256>>>(x, w1, w2);

    // fused GEMM1+GEMM2 with cross-role row-block dependency flags
    mlp_fused<<<G1_CTAS + G2_CTAS, 256, DYN_SMEM>>>(xh, w1t, w2t, b1, b2, h1, S);

    chunk_logits_kernel<<<NCHUNK, 256>>>(w3, b3, out);
    stats_kernel<<<1, 128>>>(out);
    rw_kernel<<<128, 256>>>(out);
}